// round 9
// baseline (speedup 1.0000x reference)
#include <cuda_runtime.h>
#include <cstdint>

#define GN    8192
#define LMBD  0.1f
#define QCAP  64
#define QEFF  (QCAP - 4)
#define FULLM 0xffffffffu

__device__ float    g_sum;     // zero-init; reset by last block each launch
__device__ unsigned g_count;

// R7 structure (best measured: 76.3us), micro-optimized:
//  - chunk-0 A loads hoisted above yi setup (overlap DRAM latency with setup)
//  - dual-accumulator dot8 (shorter FMA chain)
// One block per row (8192 x 256). Warp w owns cols [w*1024,(w+1)*1024) in 2
// chunks of 4 float4/lane; chunk-1 loads in flight during drain of chunk 0.
// Compaction: 1 ballot/float4, first nz queued as scalar (a, j); extras and
// overflow inline (rare). Drain: 16-lane dot groups, 4 entries/iter with all
// 8 W-loads batched before the two independent reduces. b folded via ci.
__global__ void __launch_bounds__(256, 5)
main_kernel(const float* __restrict__ A, const float* __restrict__ W,
            const float* __restrict__ b, float* __restrict__ out) {
    __shared__ float qa[8][QCAP];
    __shared__ int   qj[8][QCAP];
    __shared__ float sp[8];

    const int row  = blockIdx.x;
    const int w    = threadIdx.x >> 5;
    const int lane = threadIdx.x & 31;
    const int hl   = lane & 15;    // lane within 16-lane group
    const int grp  = lane >> 4;    // group 0..1
    const unsigned ltm = (1u << lane) - 1u;

    const float4* __restrict__ A4 =
        reinterpret_cast<const float4*>(A) + (size_t)row * (GN / 4);
    const float4* __restrict__ W4 = reinterpret_cast<const float4*>(W);
    const float4* __restrict__ B4 = reinterpret_cast<const float4*>(b);

    const int base4 = w * 256;
    float4 av[4];

    // ---- chunk-0 A loads FIRST: DRAM latency overlaps all of yi setup ----
    #pragma unroll
    for (int k = 0; k < 4; k++) av[k] = __ldcs(A4 + base4 + k * 32 + lane);

    // yi = W[row]+b: lane holds float4 indices {hl, hl+16} (8 elems),
    // replicated across the 2 groups. ci = b.yi, rn = ||yi||^2.
    float4 yi0, yi1;
    float ci, rn;
    {
        float4 wv0 = W4[row * 32 + hl],      bv0 = B4[hl];
        float4 wv1 = W4[row * 32 + 16 + hl], bv1 = B4[16 + hl];
        yi0.x = wv0.x + bv0.x; yi0.y = wv0.y + bv0.y;
        yi0.z = wv0.z + bv0.z; yi0.w = wv0.w + bv0.w;
        yi1.x = wv1.x + bv1.x; yi1.y = wv1.y + bv1.y;
        yi1.z = wv1.z + bv1.z; yi1.w = wv1.w + bv1.w;
        float c0 = bv0.x*yi0.x + bv0.y*yi0.y + bv0.z*yi0.z + bv0.w*yi0.w;
        float c1 = bv1.x*yi1.x + bv1.y*yi1.y + bv1.z*yi1.z + bv1.w*yi1.w;
        float r0 = yi0.x*yi0.x + yi0.y*yi0.y + yi0.z*yi0.z + yi0.w*yi0.w;
        float r1 = yi1.x*yi1.x + yi1.y*yi1.y + yi1.z*yi1.z + yi1.w*yi1.w;
        ci = c0 + c1; rn = r0 + r1;
        #pragma unroll
        for (int off = 1; off < 16; off <<= 1) {
            ci += __shfl_xor_sync(FULLM, ci, off);
            rn += __shfl_xor_sync(FULLM, rn, off);
        }
    }

    // reduce 8 per-lane products over the 16-lane group (valid on all lanes)
    auto dot8 = [&](float4 z0, float4 z1) -> float {
        float p0 = z0.x*yi0.x + z0.y*yi0.y + z0.z*yi0.z + z0.w*yi0.w;
        float p1 = z1.x*yi1.x + z1.y*yi1.y + z1.z*yi1.z + z1.w*yi1.w;
        float p = p0 + p1;
        p += __shfl_xor_sync(FULLM, p, 1);
        p += __shfl_xor_sync(FULLM, p, 2);
        p += __shfl_xor_sync(FULLM, p, 4);
        p += __shfl_xor_sync(FULLM, p, 8);
        return p;
    };

    float acc = (w == 0 && lane == 0) ? 0.5f * LMBD * rn : 0.f;

    int cnt = 0;   // warp-uniform

    // compact one float4: queue first nz as scalar; extras/overflow inline
    auto compact = [&](float4 a4, int g4) {
        unsigned nzm = (a4.x > 0.f ? 1u : 0u) | (a4.y > 0.f ? 2u : 0u)
                     | (a4.z > 0.f ? 4u : 0u) | (a4.w > 0.f ? 8u : 0u);
        bool nz = nzm != 0u;
        unsigned m = __ballot_sync(FULLM, nz);
        if (m == 0) return;

        int e0 = __ffs(nzm) - 1;
        float a0 = (e0 <= 0) ? a4.x : (e0 == 1) ? a4.y
                 : (e0 == 2) ? a4.z : a4.w;
        int pos = cnt + __popc(m & ltm);
        bool ovf = nz && pos >= QEFF;
        if (nz && !ovf) { qa[w][pos] = a0; qj[w][pos] = g4 * 4 + e0; }

        unsigned extra = nz ? (nzm & (nzm - 1u)) : 0u;
        unsigned mo = __ballot_sync(FULLM, (extra != 0u) | ovf);
        cnt = min(cnt + __popc(m), QEFF);
        while (mo) {   // rare
            int src = __ffs(mo) - 1; mo &= mo - 1;
            float bx = __shfl_sync(FULLM, a4.x, src);
            float by = __shfl_sync(FULLM, a4.y, src);
            float bz = __shfl_sync(FULLM, a4.z, src);
            float bw = __shfl_sync(FULLM, a4.w, src);
            unsigned em = __shfl_sync(FULLM, extra, src);
            unsigned nm = __shfl_sync(FULLM, nzm, src);
            int  ov = __shfl_sync(FULLM, (int)ovf, src);
            int  jb = __shfl_sync(FULLM, g4, src) * 4;
            unsigned todo = ov ? nm : em;
            while (todo) {
                int e = __ffs(todo) - 1; todo &= todo - 1;
                float a = (e == 0) ? bx : (e == 1) ? by : (e == 2) ? bz : bw;
                const float4* yr = W4 + (jb + e) * 32 + hl;
                float p = dot8(yr[0], yr[16]);   // same j both groups -> full dot
                if (lane == 0) {
                    float rr = a - (p + ci);
                    acc = fmaf(0.5f * rr, rr, acc);
                }
            }
        }
    };

    // drain queue: 4 entries per iteration, all 8 W-loads before any reduce
    auto drain = [&]() {
        int cntp = (cnt + 3) & ~3;
        if (lane < cntp - cnt) { qa[w][cnt + lane] = 0.f; qj[w][cnt + lane] = 0; }
        __syncwarp();
        for (int base = 0; base < cntp; base += 4) {
            float aA = qa[w][base + grp];       int jA = qj[w][base + grp];
            float aB = qa[w][base + 2 + grp];   int jB = qj[w][base + 2 + grp];
            const float4* ya = W4 + jA * 32 + hl;
            const float4* yb = W4 + jB * 32 + hl;
            float4 za0 = ya[0],  za1 = ya[16];
            float4 zb0 = yb[0],  zb1 = yb[16];
            float pA = dot8(za0, za1);
            if (aA > 0.f && hl == 0) {
                float rr = aA - (pA + ci);
                acc = fmaf(0.5f * rr, rr, acc);
            }
            float pB = dot8(zb0, zb1);
            if (aB > 0.f && hl == 0) {
                float rr = aB - (pB + ci);
                acc = fmaf(0.5f * rr, rr, acc);
            }
        }
        __syncwarp();
        cnt = 0;
    };

    // compact chunk 0 (loads issued at the very top)
    #pragma unroll
    for (int k = 0; k < 4; k++) compact(av[k], base4 + k * 32 + lane);
    // chunk 1 loads in flight before draining chunk 0
    #pragma unroll
    for (int k = 0; k < 4; k++) av[k] = __ldcs(A4 + base4 + 128 + k * 32 + lane);
    drain();
    #pragma unroll
    for (int k = 0; k < 4; k++) compact(av[k], base4 + 128 + k * 32 + lane);
    drain();

    // block reduce (acc lives on lanes 0 and 16)
    #pragma unroll
    for (int off = 16; off > 0; off >>= 1)
        acc += __shfl_xor_sync(FULLM, acc, off);
    if (lane == 0) sp[w] = acc;
    __syncthreads();

    if (threadIdx.x == 0) {
        float part = 0.f;
        #pragma unroll
        for (int i = 0; i < 8; i++) part += sp[i];
        atomicAdd(&g_sum, part);
        __threadfence();
        unsigned c = atomicAdd(&g_count, 1u);
        if (c == gridDim.x - 1) {
            float total = atomicExch(&g_sum, 0.f);
            atomicExch(&g_count, 0u);
            out[0] = total;
        }
    }
}

extern "C" void kernel_launch(void* const* d_in, const int* in_sizes, int n_in,
                              void* d_out, int out_size) {
    const float* A = (const float*)d_in[0];
    const float* W = (const float*)d_in[1];
    const float* b = (const float*)d_in[2];
    float* out = (float*)d_out;

    main_kernel<<<GN, 256>>>(A, W, b, out);
}

// round 10
// speedup vs baseline: 1.4702x; 1.4702x over previous
#include <cuda_runtime.h>
#include <cstdint>

#define GN    8192
#define LMBD  0.1f
#define QCAP  64
#define QEFF  (QCAP - 4)
#define FULLM 0xffffffffu

__device__ float    g_sum;     // zero-init; reset by last block each launch
__device__ unsigned g_count;

// R7 structure (best measured: 76.3us) with ONE fix: A-loads issued right
// after the yi/b L2 loads (not after the ci/rn shuffle chain), so the L1tex
// in-order completion queue drains the L2 hits first and the DRAM latency of
// the A-loads overlaps the ~500-cycle setup chain instead of being exposed.
// One block per row (8192 x 256). Warp w owns cols [w*1024,(w+1)*1024) in 2
// chunks of 4 float4/lane; chunk-1 loads in flight during drain of chunk 0.
// Compaction: 1 ballot/float4, first nz queued as scalar (a, j); extras and
// overflow inline (rare). Drain: 16-lane dot groups, 4 entries/iter with all
// 8 W-loads batched before the two reduces. b folded: pred = W[j].Y[i] + ci.
__global__ void __launch_bounds__(256, 5)
main_kernel(const float* __restrict__ A, const float* __restrict__ W,
            const float* __restrict__ b, float* __restrict__ out) {
    __shared__ float qa[8][QCAP];
    __shared__ int   qj[8][QCAP];
    __shared__ float sp[8];

    const int row  = blockIdx.x;
    const int w    = threadIdx.x >> 5;
    const int lane = threadIdx.x & 31;
    const int hl   = lane & 15;    // lane within 16-lane group
    const int grp  = lane >> 4;    // group 0..1
    const unsigned ltm = (1u << lane) - 1u;

    const float4* __restrict__ A4 =
        reinterpret_cast<const float4*>(A) + (size_t)row * (GN / 4);
    const float4* __restrict__ W4 = reinterpret_cast<const float4*>(W);
    const float4* __restrict__ B4 = reinterpret_cast<const float4*>(b);

    const int base4 = w * 256;
    float4 av[4];

    // L2 loads FIRST (drain early from the in-order L1tex queue) ...
    float4 wv0 = W4[row * 32 + hl];
    float4 wv1 = W4[row * 32 + 16 + hl];
    float4 bv0 = B4[hl];
    float4 bv1 = B4[16 + hl];
    // ... then DRAM loads of chunk 0: their latency overlaps the setup chain.
    #pragma unroll
    for (int k = 0; k < 4; k++) av[k] = __ldcs(A4 + base4 + k * 32 + lane);

    // yi = W[row]+b: lane holds float4 indices {hl, hl+16} (8 elems),
    // replicated across the 2 groups. ci = b.yi, rn = ||yi||^2.
    float4 yi0, yi1;
    float ci, rn;
    {
        yi0.x = wv0.x + bv0.x; yi0.y = wv0.y + bv0.y;
        yi0.z = wv0.z + bv0.z; yi0.w = wv0.w + bv0.w;
        yi1.x = wv1.x + bv1.x; yi1.y = wv1.y + bv1.y;
        yi1.z = wv1.z + bv1.z; yi1.w = wv1.w + bv1.w;
        ci = bv0.x*yi0.x + bv0.y*yi0.y + bv0.z*yi0.z + bv0.w*yi0.w
           + bv1.x*yi1.x + bv1.y*yi1.y + bv1.z*yi1.z + bv1.w*yi1.w;
        rn = yi0.x*yi0.x + yi0.y*yi0.y + yi0.z*yi0.z + yi0.w*yi0.w
           + yi1.x*yi1.x + yi1.y*yi1.y + yi1.z*yi1.z + yi1.w*yi1.w;
        #pragma unroll
        for (int off = 1; off < 16; off <<= 1) {
            ci += __shfl_xor_sync(FULLM, ci, off);
            rn += __shfl_xor_sync(FULLM, rn, off);
        }
    }

    // reduce 8 per-lane products over the 16-lane group (valid on all lanes)
    auto dot8 = [&](float4 z0, float4 z1) -> float {
        float p = z0.x*yi0.x + z0.y*yi0.y + z0.z*yi0.z + z0.w*yi0.w
                + z1.x*yi1.x + z1.y*yi1.y + z1.z*yi1.z + z1.w*yi1.w;
        p += __shfl_xor_sync(FULLM, p, 1);
        p += __shfl_xor_sync(FULLM, p, 2);
        p += __shfl_xor_sync(FULLM, p, 4);
        p += __shfl_xor_sync(FULLM, p, 8);
        return p;
    };

    float acc = (w == 0 && lane == 0) ? 0.5f * LMBD * rn : 0.f;

    int cnt = 0;   // warp-uniform

    // compact one float4: queue first nz as scalar; extras/overflow inline
    auto compact = [&](float4 a4, int g4) {
        unsigned nzm = (a4.x > 0.f ? 1u : 0u) | (a4.y > 0.f ? 2u : 0u)
                     | (a4.z > 0.f ? 4u : 0u) | (a4.w > 0.f ? 8u : 0u);
        bool nz = nzm != 0u;
        unsigned m = __ballot_sync(FULLM, nz);
        if (m == 0) return;

        int e0 = __ffs(nzm) - 1;
        float a0 = (e0 <= 0) ? a4.x : (e0 == 1) ? a4.y
                 : (e0 == 2) ? a4.z : a4.w;
        int pos = cnt + __popc(m & ltm);
        bool ovf = nz && pos >= QEFF;
        if (nz && !ovf) { qa[w][pos] = a0; qj[w][pos] = g4 * 4 + e0; }

        unsigned extra = nz ? (nzm & (nzm - 1u)) : 0u;
        unsigned mo = __ballot_sync(FULLM, (extra != 0u) | ovf);
        cnt = min(cnt + __popc(m), QEFF);
        while (mo) {   // rare
            int src = __ffs(mo) - 1; mo &= mo - 1;
            float bx = __shfl_sync(FULLM, a4.x, src);
            float by = __shfl_sync(FULLM, a4.y, src);
            float bz = __shfl_sync(FULLM, a4.z, src);
            float bw = __shfl_sync(FULLM, a4.w, src);
            unsigned em = __shfl_sync(FULLM, extra, src);
            unsigned nm = __shfl_sync(FULLM, nzm, src);
            int  ov = __shfl_sync(FULLM, (int)ovf, src);
            int  jb = __shfl_sync(FULLM, g4, src) * 4;
            unsigned todo = ov ? nm : em;
            while (todo) {
                int e = __ffs(todo) - 1; todo &= todo - 1;
                float a = (e == 0) ? bx : (e == 1) ? by : (e == 2) ? bz : bw;
                const float4* yr = W4 + (jb + e) * 32 + hl;
                float p = dot8(yr[0], yr[16]);   // same j both groups -> full dot
                if (lane == 0) {
                    float rr = a - (p + ci);
                    acc = fmaf(0.5f * rr, rr, acc);
                }
            }
        }
    };

    // drain queue: 4 entries per iteration, all 8 W-loads before any reduce
    auto drain = [&]() {
        int cntp = (cnt + 3) & ~3;
        if (lane < cntp - cnt) { qa[w][cnt + lane] = 0.f; qj[w][cnt + lane] = 0; }
        __syncwarp();
        for (int base = 0; base < cntp; base += 4) {
            float aA = qa[w][base + grp];       int jA = qj[w][base + grp];
            float aB = qa[w][base + 2 + grp];   int jB = qj[w][base + 2 + grp];
            const float4* ya = W4 + jA * 32 + hl;
            const float4* yb = W4 + jB * 32 + hl;
            float4 za0 = ya[0],  za1 = ya[16];
            float4 zb0 = yb[0],  zb1 = yb[16];
            float pA = dot8(za0, za1);
            if (aA > 0.f && hl == 0) {
                float rr = aA - (pA + ci);
                acc = fmaf(0.5f * rr, rr, acc);
            }
            float pB = dot8(zb0, zb1);
            if (aB > 0.f && hl == 0) {
                float rr = aB - (pB + ci);
                acc = fmaf(0.5f * rr, rr, acc);
            }
        }
        __syncwarp();
        cnt = 0;
    };

    // compact chunk 0 (loads already in flight from the prologue)
    #pragma unroll
    for (int k = 0; k < 4; k++) compact(av[k], base4 + k * 32 + lane);
    // chunk 1 loads in flight before draining chunk 0
    #pragma unroll
    for (int k = 0; k < 4; k++) av[k] = __ldcs(A4 + base4 + 128 + k * 32 + lane);
    drain();
    #pragma unroll
    for (int k = 0; k < 4; k++) compact(av[k], base4 + 128 + k * 32 + lane);
    drain();

    // block reduce (acc lives on lanes 0 and 16)
    #pragma unroll
    for (int off = 16; off > 0; off >>= 1)
        acc += __shfl_xor_sync(FULLM, acc, off);
    if (lane == 0) sp[w] = acc;
    __syncthreads();

    if (threadIdx.x == 0) {
        float part = 0.f;
        #pragma unroll
        for (int i = 0; i < 8; i++) part += sp[i];
        atomicAdd(&g_sum, part);
        __threadfence();
        unsigned c = atomicAdd(&g_count, 1u);
        if (c == gridDim.x - 1) {
            float total = atomicExch(&g_sum, 0.f);
            atomicExch(&g_count, 0u);
            out[0] = total;
        }
    }
}

extern "C" void kernel_launch(void* const* d_in, const int* in_sizes, int n_in,
                              void* d_out, int out_size) {
    const float* A = (const float*)d_in[0];
    const float* W = (const float*)d_in[1];
    const float* b = (const float*)d_in[2];
    float* out = (float*)d_out;

    main_kernel<<<GN, 256>>>(A, W, b, out);
}

// round 11
// speedup vs baseline: 1.6816x; 1.1438x over previous
#include <cuda_runtime.h>
#include <cstdint>

#define GN    8192
#define LMBD  0.1f
#define QCAP  64
#define QEFF  (QCAP - 4)
#define FULLM 0xffffffffu

__device__ float    g_sum;     // zero-init; reset by last block each launch
__device__ unsigned g_count;

__device__ __forceinline__ void cpa16(uint32_t dst_smem, const void* src) {
    asm volatile("cp.async.cg.shared.global [%0], [%1], 16;"
                 :: "r"(dst_smem), "l"(src));
}

// R7 compact/drain (best measured) with A staged through smem via cp.async:
// av[] registers eliminated -> 6 blocks/SM (launch_bounds 256,6).
// One block per row (8192 x 256). Warp w owns cols [w*1024,(w+1)*1024).
// W/b L2 loads issue first (FIFO lesson from R9/R10), then 8x cp.async 16B
// per lane stream the full 4KB segment to smem while the yi/ci/rn setup chain
// runs. Compact from smem (1 ballot/float4, first nz queued as scalar (a,j);
// extras/overflow inline), then ONE drain: 16-lane dot groups, 4 entries/iter,
// all 8 W-loads batched before the reduces. b folded: pred = W[j].Y[i] + ci.
__global__ void __launch_bounds__(256, 6)
main_kernel(const float* __restrict__ A, const float* __restrict__ W,
            const float* __restrict__ b, float* __restrict__ out) {
    __shared__ float4 stage[8][256];   // 8 warps x 4KB
    __shared__ float qa[8][QCAP];
    __shared__ int   qj[8][QCAP];
    __shared__ float sp[8];

    const int row  = blockIdx.x;
    const int w    = threadIdx.x >> 5;
    const int lane = threadIdx.x & 31;
    const int hl   = lane & 15;    // lane within 16-lane group
    const int grp  = lane >> 4;    // group 0..1
    const unsigned ltm = (1u << lane) - 1u;

    const float4* __restrict__ A4 =
        reinterpret_cast<const float4*>(A) + (size_t)row * (GN / 4);
    const float4* __restrict__ W4 = reinterpret_cast<const float4*>(W);
    const float4* __restrict__ B4 = reinterpret_cast<const float4*>(b);

    const int base4 = w * 256;

    // L2 loads FIRST (drain early from the in-order L1tex queue) ...
    float4 wv0 = W4[row * 32 + hl];
    float4 wv1 = W4[row * 32 + 16 + hl];
    float4 bv0 = B4[hl];
    float4 bv1 = B4[16 + hl];

    // ... then stream the whole 4KB A segment to smem (MLP=8, no registers)
    {
        uint32_t sdst = (uint32_t)__cvta_generic_to_shared(&stage[w][lane]);
        const float4* gsrc = A4 + base4 + lane;
        #pragma unroll
        for (int k = 0; k < 8; k++)
            cpa16(sdst + k * 32 * 16, gsrc + k * 32);
        asm volatile("cp.async.commit_group;");
    }

    // yi = W[row]+b: lane holds float4 indices {hl, hl+16} (8 elems),
    // replicated across the 2 groups. ci = b.yi, rn = ||yi||^2.
    float4 yi0, yi1;
    float ci, rn;
    {
        yi0.x = wv0.x + bv0.x; yi0.y = wv0.y + bv0.y;
        yi0.z = wv0.z + bv0.z; yi0.w = wv0.w + bv0.w;
        yi1.x = wv1.x + bv1.x; yi1.y = wv1.y + bv1.y;
        yi1.z = wv1.z + bv1.z; yi1.w = wv1.w + bv1.w;
        ci = bv0.x*yi0.x + bv0.y*yi0.y + bv0.z*yi0.z + bv0.w*yi0.w
           + bv1.x*yi1.x + bv1.y*yi1.y + bv1.z*yi1.z + bv1.w*yi1.w;
        rn = yi0.x*yi0.x + yi0.y*yi0.y + yi0.z*yi0.z + yi0.w*yi0.w
           + yi1.x*yi1.x + yi1.y*yi1.y + yi1.z*yi1.z + yi1.w*yi1.w;
        #pragma unroll
        for (int off = 1; off < 16; off <<= 1) {
            ci += __shfl_xor_sync(FULLM, ci, off);
            rn += __shfl_xor_sync(FULLM, rn, off);
        }
    }

    // reduce 8 per-lane products over the 16-lane group (valid on all lanes)
    auto dot8 = [&](float4 z0, float4 z1) -> float {
        float p = z0.x*yi0.x + z0.y*yi0.y + z0.z*yi0.z + z0.w*yi0.w
                + z1.x*yi1.x + z1.y*yi1.y + z1.z*yi1.z + z1.w*yi1.w;
        p += __shfl_xor_sync(FULLM, p, 1);
        p += __shfl_xor_sync(FULLM, p, 2);
        p += __shfl_xor_sync(FULLM, p, 4);
        p += __shfl_xor_sync(FULLM, p, 8);
        return p;
    };

    float acc = (w == 0 && lane == 0) ? 0.5f * LMBD * rn : 0.f;

    int cnt = 0;   // warp-uniform

    // compact one float4: queue first nz as scalar; extras/overflow inline
    auto compact = [&](float4 a4, int g4) {
        unsigned nzm = (a4.x > 0.f ? 1u : 0u) | (a4.y > 0.f ? 2u : 0u)
                     | (a4.z > 0.f ? 4u : 0u) | (a4.w > 0.f ? 8u : 0u);
        bool nz = nzm != 0u;
        unsigned m = __ballot_sync(FULLM, nz);
        if (m == 0) return;

        int e0 = __ffs(nzm) - 1;
        float a0 = (e0 <= 0) ? a4.x : (e0 == 1) ? a4.y
                 : (e0 == 2) ? a4.z : a4.w;
        int pos = cnt + __popc(m & ltm);
        bool ovf = nz && pos >= QEFF;
        if (nz && !ovf) { qa[w][pos] = a0; qj[w][pos] = g4 * 4 + e0; }

        unsigned extra = nz ? (nzm & (nzm - 1u)) : 0u;
        unsigned mo = __ballot_sync(FULLM, (extra != 0u) | ovf);
        cnt = min(cnt + __popc(m), QEFF);
        while (mo) {   // rare
            int src = __ffs(mo) - 1; mo &= mo - 1;
            float bx = __shfl_sync(FULLM, a4.x, src);
            float by = __shfl_sync(FULLM, a4.y, src);
            float bz = __shfl_sync(FULLM, a4.z, src);
            float bw = __shfl_sync(FULLM, a4.w, src);
            unsigned em = __shfl_sync(FULLM, extra, src);
            unsigned nm = __shfl_sync(FULLM, nzm, src);
            int  ov = __shfl_sync(FULLM, (int)ovf, src);
            int  jb = __shfl_sync(FULLM, g4, src) * 4;
            unsigned todo = ov ? nm : em;
            while (todo) {
                int e = __ffs(todo) - 1; todo &= todo - 1;
                float a = (e == 0) ? bx : (e == 1) ? by : (e == 2) ? bz : bw;
                const float4* yr = W4 + (jb + e) * 32 + hl;
                float p = dot8(yr[0], yr[16]);   // same j both groups -> full dot
                if (lane == 0) {
                    float rr = a - (p + ci);
                    acc = fmaf(0.5f * rr, rr, acc);
                }
            }
        }
    };

    // wait for the A segment, then compact all 8 float4 groups from smem
    asm volatile("cp.async.wait_group 0;");
    __syncwarp();
    #pragma unroll
    for (int k = 0; k < 8; k++) {
        float4 a4 = stage[w][k * 32 + lane];
        compact(a4, base4 + k * 32 + lane);
    }

    // single drain: 4 entries per iteration, all 8 W-loads before any reduce
    {
        int cntp = (cnt + 3) & ~3;
        if (lane < cntp - cnt) { qa[w][cnt + lane] = 0.f; qj[w][cnt + lane] = 0; }
        __syncwarp();
        for (int base = 0; base < cntp; base += 4) {
            float aA = qa[w][base + grp];       int jA = qj[w][base + grp];
            float aB = qa[w][base + 2 + grp];   int jB = qj[w][base + 2 + grp];
            const float4* ya = W4 + jA * 32 + hl;
            const float4* yb = W4 + jB * 32 + hl;
            float4 za0 = ya[0],  za1 = ya[16];
            float4 zb0 = yb[0],  zb1 = yb[16];
            float pA = dot8(za0, za1);
            if (aA > 0.f && hl == 0) {
                float rr = aA - (pA + ci);
                acc = fmaf(0.5f * rr, rr, acc);
            }
            float pB = dot8(zb0, zb1);
            if (aB > 0.f && hl == 0) {
                float rr = aB - (pB + ci);
                acc = fmaf(0.5f * rr, rr, acc);
            }
        }
    }

    // block reduce (acc lives on lanes 0 and 16)
    #pragma unroll
    for (int off = 16; off > 0; off >>= 1)
        acc += __shfl_xor_sync(FULLM, acc, off);
    if (lane == 0) sp[w] = acc;
    __syncthreads();

    if (threadIdx.x == 0) {
        float part = 0.f;
        #pragma unroll
        for (int i = 0; i < 8; i++) part += sp[i];
        atomicAdd(&g_sum, part);
        __threadfence();
        unsigned c = atomicAdd(&g_count, 1u);
        if (c == gridDim.x - 1) {
            float total = atomicExch(&g_sum, 0.f);
            atomicExch(&g_count, 0u);
            out[0] = total;
        }
    }
}

extern "C" void kernel_launch(void* const* d_in, const int* in_sizes, int n_in,
                              void* d_out, int out_size) {
    const float* A = (const float*)d_in[0];
    const float* W = (const float*)d_in[1];
    const float* b = (const float*)d_in[2];
    float* out = (float*)d_out;

    main_kernel<<<GN, 256>>>(A, W, b, out);
}